// round 3
// baseline (speedup 1.0000x reference)
#include <cuda_runtime.h>
#include <math.h>

#define BATCH 256
#define DIM   512
#define NCLS  100000
#define NSUB  3
#define MROWS (NCLS*NSUB)

#define BM 48
#define BK 32

#define CPC 125
#define NCHUNK (NCLS/CPC)   // 800 exactly

// ArcFace constants (margin = 0.5)
#define COS_M 0.8775825618903728f
#define SIN_M 0.479425538604203f
#define TH_C  (-0.8775825618903728f)
#define MM_C  0.2397127693021015f
#define SCALE_C 64.0f

// ---------------- scratch (device globals; no allocation allowed) ----------
__device__ float g_eT[DIM * BATCH];            // embeddings normalized, [k][n]
__device__ float g_inv_wn[MROWS];              // 1/max(||w_row||, eps)
__device__ float g_cos[(size_t)NCLS * BATCH];  // [class][n] max-over-subcenter cosine
__device__ float g_pm[NCHUNK * BATCH];
__device__ float g_ps[NCHUNK * BATCH];
__device__ float g_lab_logit[BATCH];
__device__ int   g_labels[BATCH];

// ---------------- label decode (int32 vs int64 robust) ---------------------
__global__ void k_decode_labels(const int* __restrict__ p) {
    __shared__ int any_nonzero;
    int t = threadIdx.x;
    if (t == 0) any_nonzero = 0;
    __syncthreads();
    // First 256 int32 words are in-bounds for both layouts (>=1KB buffer).
    // int64 layout: odd words are high halves == 0 (labels < 100000).
    if (t < 128) {
        if (p[2 * t + 1] != 0) any_nonzero = 1;
    }
    __syncthreads();
    if (any_nonzero) g_labels[t] = p[t];        // int32 labels
    else             g_labels[t] = p[2 * t];    // int64 labels (low word)
}

// ---------------- embedding normalize (transposed output) ------------------
__global__ void k_norm_emb(const float* __restrict__ emb) {
    int n = blockIdx.x, tid = threadIdx.x;     // 128 threads
    float v[4];
    float ss = 0.f;
#pragma unroll
    for (int i = 0; i < 4; i++) {
        v[i] = emb[n * DIM + tid + i * 128];
        ss += v[i] * v[i];
    }
#pragma unroll
    for (int o = 16; o; o >>= 1) ss += __shfl_xor_sync(0xffffffffu, ss, o);
    __shared__ float swarp[4];
    __shared__ float sinv;
    if ((tid & 31) == 0) swarp[tid >> 5] = ss;
    __syncthreads();
    if (tid == 0)
        sinv = 1.f / fmaxf(sqrtf(swarp[0] + swarp[1] + swarp[2] + swarp[3]), 1e-12f);
    __syncthreads();
    float inv = sinv;
#pragma unroll
    for (int i = 0; i < 4; i++)
        g_eT[(tid + i * 128) * BATCH + n] = v[i] * inv;
}

// ---------------- weight row inverse norms (warp per row) ------------------
__global__ void k_wnorm(const float* __restrict__ W) {
    int warp = threadIdx.x >> 5, lane = threadIdx.x & 31;
    int row = blockIdx.x * 8 + warp;
    const float4* p = (const float4*)(W + (size_t)row * DIM);
    float ss = 0.f;
#pragma unroll
    for (int i = 0; i < 4; i++) {
        float4 q = p[lane + i * 32];
        ss += q.x * q.x + q.y * q.y + q.z * q.z + q.w * q.w;
    }
#pragma unroll
    for (int o = 16; o; o >>= 1) ss += __shfl_xor_sync(0xffffffffu, ss, o);
    if (lane == 0) g_inv_wn[row] = 1.f / fmaxf(sqrtf(ss), 1e-12f);
}

// ---------------- fused cosine GEMM + subcenter max ------------------------
// Block: 48 weight rows (16 classes) x all 256 batch cols, K = 512.
// 256 threads: tm = tid/32 (8 row-groups of 6 rows), tn = tid%32 (8 cols each).
__global__ void __launch_bounds__(256, 2) k_gemm(const float* __restrict__ W) {
    __shared__ float As[BK][BM + 1];   // [k][m], padded: conflict-free
    __shared__ float Bs[BK][BATCH];    // [k][n]
    int tid = threadIdx.x;
    int m0 = blockIdx.x * BM;
    int tm = tid >> 5, tn = tid & 31;
    const float* Wb = W + (size_t)m0 * DIM;

    float acc[6][8];
#pragma unroll
    for (int i = 0; i < 6; i++)
#pragma unroll
        for (int j = 0; j < 8; j++) acc[i][j] = 0.f;

    for (int k0 = 0; k0 < DIM; k0 += BK) {
        // A tile: 48x32, coalesced global reads, transposed store
#pragma unroll
        for (int i = 0; i < 6; i++) {
            int e = tid + i * 256;
            int r = e >> 5, c = e & 31;
            As[c][r] = Wb[(size_t)r * DIM + k0 + c];
        }
        // B tile: 32x256, fully coalesced (eT is [k][n])
#pragma unroll
        for (int i = 0; i < BK; i++)
            Bs[i][tid] = g_eT[(k0 + i) * BATCH + tid];
        __syncthreads();

#pragma unroll
        for (int kk = 0; kk < BK; kk++) {
            float a[6], b[8];
#pragma unroll
            for (int i = 0; i < 6; i++) a[i] = As[kk][tm * 6 + i];  // broadcast
            float4 b0 = *(const float4*)&Bs[kk][tn * 8];
            float4 b1 = *(const float4*)&Bs[kk][tn * 8 + 4];
            b[0] = b0.x; b[1] = b0.y; b[2] = b0.z; b[3] = b0.w;
            b[4] = b1.x; b[5] = b1.y; b[6] = b1.z; b[7] = b1.w;
#pragma unroll
            for (int i = 0; i < 6; i++)
#pragma unroll
                for (int j = 0; j < 8; j++)
                    acc[i][j] = fmaf(a[i], b[j], acc[i][j]);
        }
        __syncthreads();
    }

    // Epilogue: apply weight inv-norm, max over 3 subcenters, coalesced store
    float inv[6];
#pragma unroll
    for (int i = 0; i < 6; i++) inv[i] = g_inv_wn[m0 + tm * 6 + i];
    int cls0 = (m0 + tm * 6) / 3;   // tm*6 divisible by 3: 2 whole classes
#pragma unroll
    for (int cl = 0; cl < 2; cl++) {
        int b = cl * 3;
        float out[8];
#pragma unroll
        for (int j = 0; j < 8; j++) {
            float c0 = acc[b][j] * inv[b];
            float c1 = acc[b + 1][j] * inv[b + 1];
            float c2 = acc[b + 2][j] * inv[b + 2];
            out[j] = fmaxf(c0, fmaxf(c1, c2));
        }
        float* dst = &g_cos[(size_t)(cls0 + cl) * BATCH + tn * 8];
        *(float4*)dst       = make_float4(out[0], out[1], out[2], out[3]);
        *(float4*)(dst + 4) = make_float4(out[4], out[5], out[6], out[7]);
    }
}

// ---------------- chunked online logsumexp with ArcFace margin -------------
__global__ void k_lse(void) {
    int t = threadIdx.x;               // batch index
    int c0 = blockIdx.x * CPC;
    int c1 = c0 + CPC;
    int lab = g_labels[t];
    float m = -1e30f, s = 0.f;
    for (int c = c0; c < c1; c++) {
        float cs = g_cos[(size_t)c * BATCH + t];   // coalesced across t
        float x;
        if (c == lab) {
            float sine = sqrtf(fminf(fmaxf(1.f - cs * cs, 0.f), 1.f));
            float phi = cs * COS_M - sine * SIN_M;
            if (!(cs > TH_C)) phi = cs - MM_C;
            x = SCALE_C * phi;
            g_lab_logit[t] = x;
        } else {
            x = SCALE_C * cs;
        }
        if (x > m) { s *= __expf(m - x); m = x; }
        s += __expf(x - m);
    }
    g_pm[blockIdx.x * BATCH + t] = m;
    g_ps[blockIdx.x * BATCH + t] = s;
}

// ---------------- combine partials, mean loss ------------------------------
__global__ void k_final(float* __restrict__ out) {
    int t = threadIdx.x;               // 256 threads
    float m = -1e30f, s = 0.f;
    for (int k = 0; k < NCHUNK; k++) {
        float pm = g_pm[k * BATCH + t];
        float ps = g_ps[k * BATCH + t];
        if (pm > m) { s = s * __expf(m - pm) + ps; m = pm; }
        else        { s += ps * __expf(pm - m); }
    }
    float loss = m + logf(s) - g_lab_logit[t];
#pragma unroll
    for (int o = 16; o; o >>= 1) loss += __shfl_xor_sync(0xffffffffu, loss, o);
    __shared__ float swarp[8];
    if ((t & 31) == 0) swarp[t >> 5] = loss;
    __syncthreads();
    if (t == 0) {
        float tot = 0.f;
#pragma unroll
        for (int i = 0; i < 8; i++) tot += swarp[i];
        out[0] = tot / (float)BATCH;
    }
}

// ---------------------------------------------------------------------------
extern "C" void kernel_launch(void* const* d_in, const int* in_sizes, int n_in,
                              void* d_out, int out_size) {
    const float* emb    = (const float*)d_in[0];   // [256,512] f32
    const int*   labels = (const int*)d_in[1];     // int32 or int64, decoded
    const float* W      = (const float*)d_in[2];   // [300000,512] f32

    k_decode_labels<<<1, BATCH>>>(labels);
    k_norm_emb<<<BATCH, 128>>>(emb);
    k_wnorm<<<MROWS / 8, 256>>>(W);
    k_gemm<<<MROWS / BM, 256>>>(W);
    k_lse<<<NCHUNK, BATCH>>>();
    k_final<<<1, BATCH>>>((float*)d_out);
}

// round 5
// speedup vs baseline: 2.6999x; 2.6999x over previous
#include <cuda_runtime.h>
#include <cuda_bf16.h>
#include <math.h>
#include <stdint.h>

#define BATCH  256
#define DIM    512
#define NCLS   100000
#define MROWS  300000
#define BM     144                 // weight rows per tile = 48 classes
#define NT     2084                // ceil(300000/144)
#define KCH    32
#define NCHUNK 16                  // 512/32

// ArcFace constants (margin = 0.5)
#define COS_M 0.8775825618903728f
#define SIN_M 0.479425538604203f
#define TH_C  (-0.8775825618903728f)
#define MM_C  0.2397127693021015f

// smem stage layout (bytes): Wh | Wl | Eh | El, padded rows of 80B (40 halfs)
#define WH_OFF 0
#define WL_OFF 11520               // 144*80
#define EH_OFF 23040
#define EL_OFF 43520               // +256*80
#define STAGE  64000               // +256*80
#define CPAD   264                 // epilogue C row stride (floats)
#define SMEM_DYN (BM * CPAD * 4)   // 152064 >= 2*STAGE=128000

#define CP_ASYNC16(dst, src) \
    asm volatile("cp.async.cg.shared.global [%0], [%1], 16;" :: "r"(dst), "l"(src) : "memory")
#define CP_COMMIT() asm volatile("cp.async.commit_group;" ::: "memory")
#define CP_WAIT0()  asm volatile("cp.async.wait_group 0;" ::: "memory")

static __device__ __forceinline__ void mma16816(float* d, const uint32_t* a, const uint32_t* b) {
    asm volatile("mma.sync.aligned.m16n8k16.row.col.f32.bf16.bf16.f32 "
                 "{%0,%1,%2,%3}, {%4,%5,%6,%7}, {%8,%9}, {%0,%1,%2,%3};"
                 : "+f"(d[0]), "+f"(d[1]), "+f"(d[2]), "+f"(d[3])
                 : "r"(a[0]), "r"(a[1]), "r"(a[2]), "r"(a[3]), "r"(b[0]), "r"(b[1]));
}

// ---------------- scratch ----------------
__device__ __align__(16) __nv_bfloat16 g_Ehi[BATCH * DIM];
__device__ __align__(16) __nv_bfloat16 g_Elo[BATCH * DIM];
__device__ float g_ps[(size_t)NT * BATCH];
__device__ float g_lab[BATCH];
__device__ int   g_labels[BATCH];

// ---------------- labels (int32 vs int64 robust) ----------------
__global__ void k_decode_labels(const int* __restrict__ p) {
    __shared__ int any_nz;
    int t = threadIdx.x;
    if (t == 0) any_nz = 0;
    __syncthreads();
    if (t < 128 && p[2 * t + 1] != 0) any_nz = 1;
    __syncthreads();
    g_labels[t] = any_nz ? p[t] : p[2 * t];
}

// ---------------- normalize embeddings -> bf16 hi/lo ----------------
__global__ void k_prep(const float* __restrict__ emb) {
    int n = blockIdx.x, tid = threadIdx.x;   // 128 threads
    float v[4], ss = 0.f;
#pragma unroll
    for (int i = 0; i < 4; i++) {
        v[i] = emb[n * DIM + tid + i * 128];
        ss += v[i] * v[i];
    }
#pragma unroll
    for (int o = 16; o; o >>= 1) ss += __shfl_xor_sync(0xffffffffu, ss, o);
    __shared__ float sw[4];
    __shared__ float sinv;
    if ((tid & 31) == 0) sw[tid >> 5] = ss;
    __syncthreads();
    if (tid == 0) sinv = 1.f / fmaxf(sqrtf(sw[0] + sw[1] + sw[2] + sw[3]), 1e-12f);
    __syncthreads();
    float inv = sinv;
#pragma unroll
    for (int i = 0; i < 4; i++) {
        float x = v[i] * inv;
        __nv_bfloat16 h = __float2bfloat16(x);
        __nv_bfloat16 l = __float2bfloat16(x - __bfloat162float(h));
        g_Ehi[n * DIM + tid + i * 128] = h;
        g_Elo[n * DIM + tid + i * 128] = l;
    }
}

// ---------------- fused: bf16x3 MMA GEMM + wnorm + max3 + softmax ----------
__global__ void __launch_bounds__(384, 1) k_gemm(const float* __restrict__ W) {
    extern __shared__ char smem[];
    __shared__ float s_inv[BM];
    int t = threadIdx.x;
    int lane = t & 31, warp = t >> 5;
    int warpM = warp % 3, warpN = warp / 3;     // 3M x 4N warp grid

    size_t wbase = (size_t)blockIdx.x * BM;
    float ssq[3] = {0.f, 0.f, 0.f};
    float acc[3][8][4];
#pragma unroll
    for (int i = 0; i < 3; i++)
#pragma unroll
        for (int j = 0; j < 8; j++)
#pragma unroll
            for (int k = 0; k < 4; k++) acc[i][j][k] = 0.f;

    uint32_t sbase = (uint32_t)__cvta_generic_to_shared(smem);

    // ---- prologue: chunk 0 into stage 0 ----
    {
        float4 wreg[3];
#pragma unroll
        for (int j = 0; j < 3; j++) {
            int i = t + 384 * j, row = i >> 3, c4 = i & 7;
            size_t rg = wbase + row;
            wreg[j] = (rg < (size_t)MROWS) ? *(const float4*)(W + rg * DIM + c4 * 4)
                                           : make_float4(0.f, 0.f, 0.f, 0.f);
        }
#pragma unroll
        for (int i = 0; i < 6; i++) {
            int j = t + 384 * i;
            if (j < 2048) {
                int buf = j >> 10, r = (j & 1023) >> 2, seg = j & 3;
                const __nv_bfloat16* src = (buf ? g_Elo : g_Ehi) + r * DIM + seg * 8;
                CP_ASYNC16(sbase + (buf ? EL_OFF : EH_OFF) + r * 80 + seg * 16, src);
            }
        }
        CP_COMMIT();
#pragma unroll
        for (int j = 0; j < 3; j++) {
            int i = t + 384 * j, row = i >> 3, c4 = i & 7;
            float4 q = wreg[j];
            ssq[j] = fmaf(q.x, q.x, fmaf(q.y, q.y, fmaf(q.z, q.z, fmaf(q.w, q.w, ssq[j]))));
            __nv_bfloat162 h0 = __floats2bfloat162_rn(q.x, q.y);
            __nv_bfloat162 h1 = __floats2bfloat162_rn(q.z, q.w);
            __nv_bfloat162 l0 = __floats2bfloat162_rn(q.x - __low2float(h0), q.y - __high2float(h0));
            __nv_bfloat162 l1 = __floats2bfloat162_rn(q.z - __low2float(h1), q.w - __high2float(h1));
            uint2 uh, ul;
            uh.x = *(uint32_t*)&h0; uh.y = *(uint32_t*)&h1;
            ul.x = *(uint32_t*)&l0; ul.y = *(uint32_t*)&l1;
            *(uint2*)(smem + WH_OFF + row * 80 + c4 * 8) = uh;
            *(uint2*)(smem + WL_OFF + row * 80 + c4 * 8) = ul;
        }
        CP_WAIT0();
        __syncthreads();
    }

    // ---- mainloop ----
    for (int c = 0; c < NCHUNK; c++) {
        const char* cur = smem + (c & 1) * STAGE;
        char* nxt = smem + ((c + 1) & 1) * STAGE;
        uint32_t nxt_s = sbase + ((c + 1) & 1) * STAGE;
        float4 wreg[3];
        if (c + 1 < NCHUNK) {
#pragma unroll
            for (int j = 0; j < 3; j++) {
                int i = t + 384 * j, row = i >> 3, c4 = i & 7;
                size_t rg = wbase + row;
                wreg[j] = (rg < (size_t)MROWS)
                              ? *(const float4*)(W + rg * DIM + (c + 1) * KCH + c4 * 4)
                              : make_float4(0.f, 0.f, 0.f, 0.f);
            }
#pragma unroll
            for (int i = 0; i < 6; i++) {
                int j = t + 384 * i;
                if (j < 2048) {
                    int buf = j >> 10, r = (j & 1023) >> 2, seg = j & 3;
                    const __nv_bfloat16* src =
                        (buf ? g_Elo : g_Ehi) + r * DIM + (c + 1) * KCH + seg * 8;
                    CP_ASYNC16(nxt_s + (buf ? EL_OFF : EH_OFF) + r * 80 + seg * 16, src);
                }
            }
            CP_COMMIT();
        }

        // compute chunk c: 2 k-steps x 3 passes (Wh*Eh, Wl*Eh, Wh*El)
#pragma unroll
        for (int ks = 0; ks < 2; ks++) {
#pragma unroll
            for (int p = 0; p < 3; p++) {
                const char* Wb = cur + (p == 1 ? WL_OFF : WH_OFF) + ks * 32 + (lane & 3) * 4;
                const char* Eb = cur + (p == 2 ? EL_OFF : EH_OFF) + ks * 32 + (lane & 3) * 4;
                uint32_t bf[8][2];
                int nb = warpN * 64 + (lane >> 2);
#pragma unroll
                for (int nt = 0; nt < 8; nt++) {
                    const char* ad = Eb + (nb + nt * 8) * 80;
                    bf[nt][0] = *(const uint32_t*)ad;
                    bf[nt][1] = *(const uint32_t*)(ad + 16);
                }
                int rb = warpM * 48 + (lane >> 2);
#pragma unroll
                for (int mt = 0; mt < 3; mt++) {
                    uint32_t af[4];
                    const char* ar = Wb + (rb + mt * 16) * 80;
                    af[0] = *(const uint32_t*)ar;
                    af[1] = *(const uint32_t*)(ar + 8 * 80);
                    af[2] = *(const uint32_t*)(ar + 16);
                    af[3] = *(const uint32_t*)(ar + 8 * 80 + 16);
#pragma unroll
                    for (int nt = 0; nt < 8; nt++) mma16816(acc[mt][nt], af, bf[nt]);
                }
            }
        }

        if (c + 1 < NCHUNK) {
#pragma unroll
            for (int j = 0; j < 3; j++) {
                int i = t + 384 * j, row = i >> 3, c4 = i & 7;
                float4 q = wreg[j];
                ssq[j] = fmaf(q.x, q.x, fmaf(q.y, q.y, fmaf(q.z, q.z, fmaf(q.w, q.w, ssq[j]))));
                __nv_bfloat162 h0 = __floats2bfloat162_rn(q.x, q.y);
                __nv_bfloat162 h1 = __floats2bfloat162_rn(q.z, q.w);
                __nv_bfloat162 l0 = __floats2bfloat162_rn(q.x - __low2float(h0), q.y - __high2float(h0));
                __nv_bfloat162 l1 = __floats2bfloat162_rn(q.z - __low2float(h1), q.w - __high2float(h1));
                uint2 uh, ul;
                uh.x = *(uint32_t*)&h0; uh.y = *(uint32_t*)&h1;
                ul.x = *(uint32_t*)&l0; ul.y = *(uint32_t*)&l1;
                *(uint2*)(nxt + WH_OFF + row * 80 + c4 * 8) = uh;
                *(uint2*)(nxt + WL_OFF + row * 80 + c4 * 8) = ul;
            }
            CP_WAIT0();
        }
        __syncthreads();
    }

    // ---- weight inv-norms (ssq: lanes sharing a row are 8 consecutive) ----
#pragma unroll
    for (int j = 0; j < 3; j++) {
        float v = ssq[j];
        v += __shfl_xor_sync(0xffffffffu, v, 4);
        v += __shfl_xor_sync(0xffffffffu, v, 2);
        v += __shfl_xor_sync(0xffffffffu, v, 1);
        if ((t & 7) == 0) s_inv[(t >> 3) + 48 * j] = 1.f / fmaxf(sqrtf(v), 1e-12f);
    }

    // ---- dump acc to smem C (aliases stages; all compute done) ----
    float* C = (float*)smem;
#pragma unroll
    for (int mt = 0; mt < 3; mt++)
#pragma unroll
        for (int nt = 0; nt < 8; nt++) {
            int rr = warpM * 48 + mt * 16 + (lane >> 2);
            int cc = warpN * 64 + nt * 8 + 2 * (lane & 3);
            *(float2*)&C[rr * CPAD + cc] = make_float2(acc[mt][nt][0], acc[mt][nt][1]);
            *(float2*)&C[(rr + 8) * CPAD + cc] = make_float2(acc[mt][nt][2], acc[mt][nt][3]);
        }
    __syncthreads();

    // ---- fused epilogue: per-thread batch column ----
    if (t < BATCH) {
        int n = t;
        int lab = g_labels[n];
        int cls0 = blockIdx.x * 48;
        float ssum = 0.f;
#pragma unroll 4
        for (int cl = 0; cl < 48; cl++) {
            int r = cl * 3;
            float c0 = C[r * CPAD + n] * s_inv[r];
            float c1 = C[(r + 1) * CPAD + n] * s_inv[r + 1];
            float c2 = C[(r + 2) * CPAD + n] * s_inv[r + 2];
            float cm = fmaxf(c0, fmaxf(c1, c2));
            int gc = cls0 + cl;
            if (gc < NCLS) {
                float x;
                if (gc == lab) {
                    float sine = sqrtf(fminf(fmaxf(1.f - cm * cm, 0.f), 1.f));
                    float phi = cm * COS_M - sine * SIN_M;
                    if (!(cm > TH_C)) phi = cm - MM_C;
                    x = 64.f * phi;
                    g_lab[n] = x;
                } else {
                    x = 64.f * cm;
                }
                ssum += __expf(x - 64.f);
            }
        }
        g_ps[(size_t)blockIdx.x * BATCH + n] = ssum;
    }
}

// ---------------- combine partials, mean loss ----------------
__global__ void k_final(float* __restrict__ out) {
    int t = threadIdx.x;  // 256
    float s = 0.f;
    for (int k = 0; k < NT; k++) s += g_ps[(size_t)k * BATCH + t];
    float loss = 64.f + logf(s) - g_lab[t];
#pragma unroll
    for (int o = 16; o; o >>= 1) loss += __shfl_xor_sync(0xffffffffu, loss, o);
    __shared__ float sw[8];
    if ((t & 31) == 0) sw[t >> 5] = loss;
    __syncthreads();
    if (t == 0) {
        float tot = 0.f;
#pragma unroll
        for (int i = 0; i < 8; i++) tot += sw[i];
        out[0] = tot / (float)BATCH;
    }
}

// ---------------------------------------------------------------------------
extern "C" void kernel_launch(void* const* d_in, const int* in_sizes, int n_in,
                              void* d_out, int out_size) {
    const float* emb    = (const float*)d_in[0];
    const int*   labels = (const int*)d_in[1];
    const float* W      = (const float*)d_in[2];

    cudaFuncSetAttribute(k_gemm, cudaFuncAttributeMaxDynamicSharedMemorySize, SMEM_DYN);

    k_decode_labels<<<1, BATCH>>>(labels);
    k_prep<<<BATCH, 128>>>(emb);
    k_gemm<<<NT, 384, SMEM_DYN>>>(W);
    k_final<<<1, BATCH>>>((float*)d_out);
}

// round 8
// speedup vs baseline: 3.0974x; 1.1472x over previous
#include <cuda_runtime.h>
#include <cuda_bf16.h>
#include <math.h>
#include <stdint.h>

#define BATCH  256
#define DIM    512
#define NCLS   100000
#define MROWS  300000
#define BM     144                 // weight rows per tile = 48 classes
#define NT     2084                // ceil(300000/144)
#define KCH    32
#define NCHUNK 16                  // 512/32
#define FBLK   64                  // reduction blocks

// ArcFace constants (margin = 0.5)
#define COS_M 0.8775825618903728f
#define SIN_M 0.479425538604203f
#define TH_C  (-0.8775825618903728f)
#define MM_C  0.2397127693021015f

// smem stage layout (bytes): Wh | Wl | Eh | El, padded rows of 80B (40 halfs)
#define WH_OFF 0
#define WL_OFF 11520               // 144*80
#define EH_OFF 23040
#define EL_OFF 43520               // +256*80
#define STAGE  64000               // +256*80
#define CPAD   264                 // epilogue C row stride (floats)
#define SMEM_DYN (BM * CPAD * 4)   // 152064 >= 2*STAGE=128000

#define CP_ASYNC16(dst, src) \
    asm volatile("cp.async.cg.shared.global [%0], [%1], 16;" :: "r"(dst), "l"(src) : "memory")
#define CP_COMMIT() asm volatile("cp.async.commit_group;" ::: "memory")
#define CP_WAIT0()  asm volatile("cp.async.wait_group 0;" ::: "memory")

#define LDSM_X4(r, a) \
    asm volatile("ldmatrix.sync.aligned.m8n8.x4.shared.b16 {%0,%1,%2,%3}, [%4];" \
        : "=r"((r)[0]), "=r"((r)[1]), "=r"((r)[2]), "=r"((r)[3]) : "r"(a))

static __device__ __forceinline__ void mma16816(float* d, const uint32_t* a, const uint32_t* b) {
    asm volatile("mma.sync.aligned.m16n8k16.row.col.f32.bf16.bf16.f32 "
                 "{%0,%1,%2,%3}, {%4,%5,%6,%7}, {%8,%9}, {%0,%1,%2,%3};"
                 : "+f"(d[0]), "+f"(d[1]), "+f"(d[2]), "+f"(d[3])
                 : "r"(a[0]), "r"(a[1]), "r"(a[2]), "r"(a[3]), "r"(b[0]), "r"(b[1]));
}

// ---------------- scratch ----------------
__device__ __align__(16) __nv_bfloat16 g_Ehi[BATCH * DIM];
__device__ __align__(16) __nv_bfloat16 g_Elo[BATCH * DIM];
__device__ float g_ps[(size_t)NT * BATCH];
__device__ float g_ps2[FBLK * BATCH];
__device__ float g_lab[BATCH];
__device__ int   g_labels[BATCH];

// ---------------- labels (int32 vs int64 robust) ----------------
__global__ void k_decode_labels(const int* __restrict__ p) {
    __shared__ int any_nz;
    int t = threadIdx.x;
    if (t == 0) any_nz = 0;
    __syncthreads();
    if (t < 128 && p[2 * t + 1] != 0) any_nz = 1;
    __syncthreads();
    g_labels[t] = any_nz ? p[t] : p[2 * t];
}

// ---------------- normalize embeddings -> bf16 hi/lo ----------------
__global__ void k_prep(const float* __restrict__ emb) {
    int n = blockIdx.x, tid = threadIdx.x;   // 128 threads
    float v[4], ss = 0.f;
#pragma unroll
    for (int i = 0; i < 4; i++) {
        v[i] = emb[n * DIM + tid + i * 128];
        ss += v[i] * v[i];
    }
#pragma unroll
    for (int o = 16; o; o >>= 1) ss += __shfl_xor_sync(0xffffffffu, ss, o);
    __shared__ float sw[4];
    __shared__ float sinv;
    if ((tid & 31) == 0) sw[tid >> 5] = ss;
    __syncthreads();
    if (tid == 0) sinv = 1.f / fmaxf(sqrtf(sw[0] + sw[1] + sw[2] + sw[3]), 1e-12f);
    __syncthreads();
    float inv = sinv;
#pragma unroll
    for (int i = 0; i < 4; i++) {
        float x = v[i] * inv;
        __nv_bfloat16 h = __float2bfloat16(x);
        __nv_bfloat16 l = __float2bfloat16(x - __bfloat162float(h));
        g_Ehi[n * DIM + tid + i * 128] = h;
        g_Elo[n * DIM + tid + i * 128] = l;
    }
}

// ---------------- fused: bf16x3 MMA GEMM + wnorm + max3 + softmax ----------
__global__ void __launch_bounds__(384, 1) k_gemm(const float* __restrict__ W) {
    extern __shared__ char smem[];
    __shared__ float s_inv[BM];
    int t = threadIdx.x;
    int lane = t & 31, warp = t >> 5;
    int warpM = warp % 3, warpN = warp / 3;     // 3M x 4N warp grid

    size_t wbase = (size_t)blockIdx.x * BM;
    float ssq[3] = {0.f, 0.f, 0.f};
    float acc[3][8][4];
#pragma unroll
    for (int i = 0; i < 3; i++)
#pragma unroll
        for (int j = 0; j < 8; j++)
#pragma unroll
            for (int k = 0; k < 4; k++) acc[i][j][k] = 0.f;

    uint32_t sbase = (uint32_t)__cvta_generic_to_shared(smem);

    // ldmatrix per-lane row offsets (g = lane>>3 selects the 8x8 matrix slot)
    int g = lane >> 3, lr = lane & 7;
    uint32_t b_row_off = (uint32_t)((warpN * 64 + ((g >> 1) << 3) + lr) * 80 + (g & 1) * 16);
    uint32_t a_row_off = (uint32_t)((warpM * 48 + ((g & 1) << 3) + lr) * 80 + (g >> 1) * 16);

    // ---- prologue: chunk 0 into stage 0 ----
    {
        float4 wreg[3];
#pragma unroll
        for (int j = 0; j < 3; j++) {
            int i = t + 384 * j, row = i >> 3, c4 = i & 7;
            size_t rg = wbase + row;
            wreg[j] = (rg < (size_t)MROWS) ? *(const float4*)(W + rg * DIM + c4 * 4)
                                           : make_float4(0.f, 0.f, 0.f, 0.f);
        }
#pragma unroll
        for (int i = 0; i < 6; i++) {
            int j = t + 384 * i;
            if (j < 2048) {
                int buf = j >> 10, r = (j & 1023) >> 2, seg = j & 3;
                const __nv_bfloat16* src = (buf ? g_Elo : g_Ehi) + r * DIM + seg * 8;
                CP_ASYNC16(sbase + (buf ? EL_OFF : EH_OFF) + r * 80 + seg * 16, src);
            }
        }
        CP_COMMIT();
#pragma unroll
        for (int j = 0; j < 3; j++) {
            int i = t + 384 * j, row = i >> 3, c4 = i & 7;
            float4 q = wreg[j];
            ssq[j] = fmaf(q.x, q.x, fmaf(q.y, q.y, fmaf(q.z, q.z, fmaf(q.w, q.w, ssq[j]))));
            __nv_bfloat162 h0 = __floats2bfloat162_rn(q.x, q.y);
            __nv_bfloat162 h1 = __floats2bfloat162_rn(q.z, q.w);
            __nv_bfloat162 l0 = __floats2bfloat162_rn(q.x - __low2float(h0), q.y - __high2float(h0));
            __nv_bfloat162 l1 = __floats2bfloat162_rn(q.z - __low2float(h1), q.w - __high2float(h1));
            uint2 uh, ul;
            uh.x = *(uint32_t*)&h0; uh.y = *(uint32_t*)&h1;
            ul.x = *(uint32_t*)&l0; ul.y = *(uint32_t*)&l1;
            *(uint2*)(smem + WH_OFF + row * 80 + c4 * 8) = uh;
            *(uint2*)(smem + WL_OFF + row * 80 + c4 * 8) = ul;
        }
        CP_WAIT0();
        __syncthreads();
    }

    // ---- mainloop ----
    for (int c = 0; c < NCHUNK; c++) {
        uint32_t sb_cur = sbase + (c & 1) * STAGE;
        char* nxt = smem + ((c + 1) & 1) * STAGE;
        uint32_t nxt_s = sbase + ((c + 1) & 1) * STAGE;
        float4 wreg[3];
        if (c + 1 < NCHUNK) {
#pragma unroll
            for (int j = 0; j < 3; j++) {
                int i = t + 384 * j, row = i >> 3, c4 = i & 7;
                size_t rg = wbase + row;
                wreg[j] = (rg < (size_t)MROWS)
                              ? *(const float4*)(W + rg * DIM + (c + 1) * KCH + c4 * 4)
                              : make_float4(0.f, 0.f, 0.f, 0.f);
            }
#pragma unroll
            for (int i = 0; i < 6; i++) {
                int j = t + 384 * i;
                if (j < 2048) {
                    int buf = j >> 10, r = (j & 1023) >> 2, seg = j & 3;
                    const __nv_bfloat16* src =
                        (buf ? g_Elo : g_Ehi) + r * DIM + (c + 1) * KCH + seg * 8;
                    CP_ASYNC16(nxt_s + (buf ? EL_OFF : EH_OFF) + r * 80 + seg * 16, src);
                }
            }
            CP_COMMIT();
        }

        // compute chunk c: 2 k-steps x 3 passes (Wh*Eh, Wl*Eh, Wh*El)
#pragma unroll
        for (int ks = 0; ks < 2; ks++) {
#pragma unroll
            for (int p = 0; p < 3; p++) {
                uint32_t Wb = sb_cur + (p == 1 ? WL_OFF : WH_OFF) + ks * 32;
                uint32_t Eb = sb_cur + (p == 2 ? EL_OFF : EH_OFF) + ks * 32;
                uint32_t bfr[4][4];
#pragma unroll
                for (int pr = 0; pr < 4; pr++)
                    LDSM_X4(bfr[pr], Eb + b_row_off + pr * (16 * 80));
#pragma unroll
                for (int mt = 0; mt < 3; mt++) {
                    uint32_t af[4];
                    LDSM_X4(af, Wb + a_row_off + mt * (16 * 80));
#pragma unroll
                    for (int nt = 0; nt < 8; nt++) {
                        uint32_t bb[2] = { bfr[nt >> 1][(nt & 1) * 2],
                                           bfr[nt >> 1][(nt & 1) * 2 + 1] };
                        mma16816(acc[mt][nt], af, bb);
                    }
                }
            }
        }

        if (c + 1 < NCHUNK) {
#pragma unroll
            for (int j = 0; j < 3; j++) {
                int i = t + 384 * j, row = i >> 3, c4 = i & 7;
                float4 q = wreg[j];
                ssq[j] = fmaf(q.x, q.x, fmaf(q.y, q.y, fmaf(q.z, q.z, fmaf(q.w, q.w, ssq[j]))));
                __nv_bfloat162 h0 = __floats2bfloat162_rn(q.x, q.y);
                __nv_bfloat162 h1 = __floats2bfloat162_rn(q.z, q.w);
                __nv_bfloat162 l0 = __floats2bfloat162_rn(q.x - __low2float(h0), q.y - __high2float(h0));
                __nv_bfloat162 l1 = __floats2bfloat162_rn(q.z - __low2float(h1), q.w - __high2float(h1));
                uint2 uh, ul;
                uh.x = *(uint32_t*)&h0; uh.y = *(uint32_t*)&h1;
                ul.x = *(uint32_t*)&l0; ul.y = *(uint32_t*)&l1;
                *(uint2*)(nxt + WH_OFF + row * 80 + c4 * 8) = uh;
                *(uint2*)(nxt + WL_OFF + row * 80 + c4 * 8) = ul;
            }
            CP_WAIT0();
        }
        __syncthreads();
    }

    // ---- weight inv-norms (ssq: lanes sharing a row are 8 consecutive) ----
#pragma unroll
    for (int j = 0; j < 3; j++) {
        float v = ssq[j];
        v += __shfl_xor_sync(0xffffffffu, v, 4);
        v += __shfl_xor_sync(0xffffffffu, v, 2);
        v += __shfl_xor_sync(0xffffffffu, v, 1);
        if ((t & 7) == 0) s_inv[(t >> 3) + 48 * j] = 1.f / fmaxf(sqrtf(v), 1e-12f);
    }

    // ---- dump acc to smem C (aliases stages; all compute done) ----
    float* C = (float*)smem;
#pragma unroll
    for (int mt = 0; mt < 3; mt++)
#pragma unroll
        for (int nt = 0; nt < 8; nt++) {
            int rr = warpM * 48 + mt * 16 + (lane >> 2);
            int cc = warpN * 64 + nt * 8 + 2 * (lane & 3);
            *(float2*)&C[rr * CPAD + cc] = make_float2(acc[mt][nt][0], acc[mt][nt][1]);
            *(float2*)&C[(rr + 8) * CPAD + cc] = make_float2(acc[mt][nt][2], acc[mt][nt][3]);
        }
    __syncthreads();

    // ---- fused epilogue: per-thread batch column ----
    if (t < BATCH) {
        int n = t;
        int lab = g_labels[n];
        int cls0 = blockIdx.x * 48;
        float ssum = 0.f;
#pragma unroll 4
        for (int cl = 0; cl < 48; cl++) {
            int r = cl * 3;
            float c0 = C[r * CPAD + n] * s_inv[r];
            float c1 = C[(r + 1) * CPAD + n] * s_inv[r + 1];
            float c2 = C[(r + 2) * CPAD + n] * s_inv[r + 2];
            float cm = fmaxf(c0, fmaxf(c1, c2));
            int gc = cls0 + cl;
            if (gc < NCLS) {
                float x;
                if (gc == lab) {
                    float sine = sqrtf(fminf(fmaxf(1.f - cm * cm, 0.f), 1.f));
                    float phi = cm * COS_M - sine * SIN_M;
                    if (!(cm > TH_C)) phi = cm - MM_C;
                    x = 64.f * phi;
                    g_lab[n] = x;
                } else {
                    x = 64.f * cm;
                }
                ssum += __expf(x - 64.f);
            }
        }
        g_ps[(size_t)blockIdx.x * BATCH + n] = ssum;
    }
}

// ---------------- two-stage reduction ----------------
__global__ void k_part(void) {
    int t = threadIdx.x, b = blockIdx.x;   // FBLK blocks x 256 threads
    int k0 = b * 33, k1 = k0 + 33;
    if (k1 > NT) k1 = NT;
    float s = 0.f;
    for (int k = k0; k < k1; k++) s += g_ps[(size_t)k * BATCH + t];
    g_ps2[b * BATCH + t] = s;
}

__global__ void k_final(float* __restrict__ out) {
    int t = threadIdx.x;  // 256
    float s = 0.f;
#pragma unroll 8
    for (int k = 0; k < FBLK; k++) s += g_ps2[k * BATCH + t];
    float loss = 64.f + logf(s) - g_lab[t];
#pragma unroll
    for (int o = 16; o; o >>= 1) loss += __shfl_xor_sync(0xffffffffu, loss, o);
    __shared__ float sw[8];
    if ((t & 31) == 0) sw[t >> 5] = loss;
    __syncthreads();
    if (t == 0) {
        float tot = 0.f;
#pragma unroll
        for (int i = 0; i < 8; i++) tot += sw[i];
        out[0] = tot / (float)BATCH;
    }
}

// ---------------------------------------------------------------------------
extern "C" void kernel_launch(void* const* d_in, const int* in_sizes, int n_in,
                              void* d_out, int out_size) {
    const float* emb    = (const float*)d_in[0];
    const int*   labels = (const int*)d_in[1];
    const float* W      = (const float*)d_in[2];

    cudaFuncSetAttribute(k_gemm, cudaFuncAttributeMaxDynamicSharedMemorySize, SMEM_DYN);

    k_decode_labels<<<1, BATCH>>>(labels);
    k_prep<<<BATCH, 128>>>(emb);
    k_gemm<<<NT, 384, SMEM_DYN>>>(W);
    k_part<<<FBLK, BATCH>>>();
    k_final<<<1, BATCH>>>((float*)d_out);
}

// round 11
// speedup vs baseline: 6.3369x; 2.0459x over previous
#include <cuda_runtime.h>
#include <cuda_bf16.h>
#include <math.h>
#include <stdint.h>

#define BATCH  256
#define DIM    512
#define NCLS   100000
#define MROWS  300000
#define BM     144                 // weight rows per tile = 48 classes
#define NT     2084                // ceil(300000/144)
#define KCH    32
#define NCHUNK 16                  // 512/32
#define FBLK   64                  // reduction blocks

// ArcFace constants (margin = 0.5)
#define COS_M 0.8775825618903728f
#define SIN_M 0.479425538604203f
#define TH_C  (-0.8775825618903728f)
#define MM_C  0.2397127693021015f

// smem stage layout (bytes): Wh | Eh, padded rows of 80B (40 halfs)
#define WH_OFF 0
#define EH_OFF 11520               // 144*80
#define STAGE  32000               // + 256*80
#define CPAD   264                 // epilogue C row stride (floats)
#define SMEM_DYN (BM * CPAD * 4)   // 152064 >= 2*STAGE=64000

#define CP_ASYNC16(dst, src) \
    asm volatile("cp.async.cg.shared.global [%0], [%1], 16;" :: "r"(dst), "l"(src) : "memory")
#define CP_COMMIT() asm volatile("cp.async.commit_group;" ::: "memory")
#define CP_WAIT0()  asm volatile("cp.async.wait_group 0;" ::: "memory")

#define LDSM_X4(r, a) \
    asm volatile("ldmatrix.sync.aligned.m8n8.x4.shared.b16 {%0,%1,%2,%3}, [%4];" \
        : "=r"((r)[0]), "=r"((r)[1]), "=r"((r)[2]), "=r"((r)[3]) : "r"(a))

static __device__ __forceinline__ void mma16816(float* d, const uint32_t* a, const uint32_t* b) {
    asm volatile("mma.sync.aligned.m16n8k16.row.col.f32.bf16.bf16.f32 "
                 "{%0,%1,%2,%3}, {%4,%5,%6,%7}, {%8,%9}, {%0,%1,%2,%3};"
                 : "+f"(d[0]), "+f"(d[1]), "+f"(d[2]), "+f"(d[3])
                 : "r"(a[0]), "r"(a[1]), "r"(a[2]), "r"(a[3]), "r"(b[0]), "r"(b[1]));
}

// ---------------- scratch ----------------
__device__ __align__(16) __nv_bfloat16 g_Ehi[BATCH * DIM];
__device__ float g_ps[(size_t)NT * BATCH];
__device__ float g_ps2[FBLK * BATCH];
__device__ float g_lab[BATCH];
__device__ int   g_labels[BATCH];

// ---------------- labels (int32 vs int64 robust) ----------------
__global__ void k_decode_labels(const int* __restrict__ p) {
    __shared__ int any_nz;
    int t = threadIdx.x;
    if (t == 0) any_nz = 0;
    __syncthreads();
    if (t < 128 && p[2 * t + 1] != 0) any_nz = 1;
    __syncthreads();
    g_labels[t] = any_nz ? p[t] : p[2 * t];
}

// ---------------- normalize embeddings -> bf16 ----------------
__global__ void k_prep(const float* __restrict__ emb) {
    int n = blockIdx.x, tid = threadIdx.x;   // 128 threads
    float v[4], ss = 0.f;
#pragma unroll
    for (int i = 0; i < 4; i++) {
        v[i] = emb[n * DIM + tid + i * 128];
        ss += v[i] * v[i];
    }
#pragma unroll
    for (int o = 16; o; o >>= 1) ss += __shfl_xor_sync(0xffffffffu, ss, o);
    __shared__ float sw[4];
    __shared__ float sinv;
    if ((tid & 31) == 0) sw[tid >> 5] = ss;
    __syncthreads();
    if (tid == 0) sinv = 1.f / fmaxf(sqrtf(sw[0] + sw[1] + sw[2] + sw[3]), 1e-12f);
    __syncthreads();
    float inv = sinv;
#pragma unroll
    for (int i = 0; i < 4; i++)
        g_Ehi[n * DIM + tid + i * 128] = __float2bfloat16(v[i] * inv);
}

// ---------------- fused: bf16 MMA GEMM + wnorm + max3 + softmax ------------
__global__ void __launch_bounds__(384, 1) k_gemm(const float* __restrict__ W) {
    extern __shared__ char smem[];
    __shared__ float s_inv[BM];
    int t = threadIdx.x;
    int lane = t & 31, warp = t >> 5;
    int warpM = warp % 3, warpN = warp / 3;     // 3M x 4N warp grid

    size_t wbase = (size_t)blockIdx.x * BM;
    float ssq[3] = {0.f, 0.f, 0.f};
    float acc[3][8][4];
#pragma unroll
    for (int i = 0; i < 3; i++)
#pragma unroll
        for (int j = 0; j < 8; j++)
#pragma unroll
            for (int k = 0; k < 4; k++) acc[i][j][k] = 0.f;

    uint32_t sbase = (uint32_t)__cvta_generic_to_shared(smem);

    // ldmatrix per-lane row offsets (g = lane>>3 selects the 8x8 matrix slot)
    int g = lane >> 3, lr = lane & 7;
    uint32_t b_row_off = (uint32_t)((warpN * 64 + ((g >> 1) << 3) + lr) * 80 + (g & 1) * 16);
    uint32_t a_row_off = (uint32_t)((warpM * 48 + ((g & 1) << 3) + lr) * 80 + (g >> 1) * 16);

    // ---- prologue: chunk 0 into stage 0 ----
    {
        float4 wreg[3];
#pragma unroll
        for (int j = 0; j < 3; j++) {
            int i = t + 384 * j, row = i >> 3, c4 = i & 7;
            size_t rg = wbase + row;
            wreg[j] = (rg < (size_t)MROWS) ? *(const float4*)(W + rg * DIM + c4 * 4)
                                           : make_float4(0.f, 0.f, 0.f, 0.f);
        }
#pragma unroll
        for (int i = 0; i < 3; i++) {
            int j = t + 384 * i;
            if (j < 1024) {
                int r = j >> 2, seg = j & 3;
                CP_ASYNC16(sbase + EH_OFF + r * 80 + seg * 16, g_Ehi + r * DIM + seg * 8);
            }
        }
        CP_COMMIT();
#pragma unroll
        for (int j = 0; j < 3; j++) {
            int i = t + 384 * j, row = i >> 3, c4 = i & 7;
            float4 q = wreg[j];
            ssq[j] = fmaf(q.x, q.x, fmaf(q.y, q.y, fmaf(q.z, q.z, fmaf(q.w, q.w, ssq[j]))));
            __nv_bfloat162 h0 = __floats2bfloat162_rn(q.x, q.y);
            __nv_bfloat162 h1 = __floats2bfloat162_rn(q.z, q.w);
            uint2 uh;
            uh.x = *(uint32_t*)&h0; uh.y = *(uint32_t*)&h1;
            *(uint2*)(smem + WH_OFF + row * 80 + c4 * 8) = uh;
        }
        CP_WAIT0();
        __syncthreads();
    }

    // ---- mainloop ----
    for (int c = 0; c < NCHUNK; c++) {
        uint32_t sb_cur = sbase + (c & 1) * STAGE;
        char* nxt = smem + ((c + 1) & 1) * STAGE;
        uint32_t nxt_s = sbase + ((c + 1) & 1) * STAGE;
        float4 wreg[3];
        if (c + 1 < NCHUNK) {
#pragma unroll
            for (int j = 0; j < 3; j++) {
                int i = t + 384 * j, row = i >> 3, c4 = i & 7;
                size_t rg = wbase + row;
                wreg[j] = (rg < (size_t)MROWS)
                              ? *(const float4*)(W + rg * DIM + (c + 1) * KCH + c4 * 4)
                              : make_float4(0.f, 0.f, 0.f, 0.f);
            }
#pragma unroll
            for (int i = 0; i < 3; i++) {
                int j = t + 384 * i;
                if (j < 1024) {
                    int r = j >> 2, seg = j & 3;
                    CP_ASYNC16(nxt_s + EH_OFF + r * 80 + seg * 16,
                               g_Ehi + r * DIM + (c + 1) * KCH + seg * 8);
                }
            }
            CP_COMMIT();
        }

        // compute chunk c: 2 k-steps, single bf16 pass
#pragma unroll
        for (int ks = 0; ks < 2; ks++) {
            uint32_t Wb = sb_cur + WH_OFF + ks * 32;
            uint32_t Eb = sb_cur + EH_OFF + ks * 32;
            uint32_t bfr[4][4];
#pragma unroll
            for (int pr = 0; pr < 4; pr++)
                LDSM_X4(bfr[pr], Eb + b_row_off + pr * (16 * 80));
#pragma unroll
            for (int mt = 0; mt < 3; mt++) {
                uint32_t af[4];
                LDSM_X4(af, Wb + a_row_off + mt * (16 * 80));
#pragma unroll
                for (int nt = 0; nt < 8; nt++) {
                    uint32_t bb[2] = { bfr[nt >> 1][(nt & 1) * 2],
                                       bfr[nt >> 1][(nt & 1) * 2 + 1] };
                    mma16816(acc[mt][nt], af, bb);
                }
            }
        }

        if (c + 1 < NCHUNK) {
#pragma unroll
            for (int j = 0; j < 3; j++) {
                int i = t + 384 * j, row = i >> 3, c4 = i & 7;
                float4 q = wreg[j];
                ssq[j] = fmaf(q.x, q.x, fmaf(q.y, q.y, fmaf(q.z, q.z, fmaf(q.w, q.w, ssq[j]))));
                __nv_bfloat162 h0 = __floats2bfloat162_rn(q.x, q.y);
                __nv_bfloat162 h1 = __floats2bfloat162_rn(q.z, q.w);
                uint2 uh;
                uh.x = *(uint32_t*)&h0; uh.y = *(uint32_t*)&h1;
                *(uint2*)(nxt + WH_OFF + row * 80 + c4 * 8) = uh;
            }
            CP_WAIT0();
        }
        __syncthreads();
    }

    // ---- weight inv-norms (ssq: lanes sharing a row are 8 consecutive) ----
#pragma unroll
    for (int j = 0; j < 3; j++) {
        float v = ssq[j];
        v += __shfl_xor_sync(0xffffffffu, v, 4);
        v += __shfl_xor_sync(0xffffffffu, v, 2);
        v += __shfl_xor_sync(0xffffffffu, v, 1);
        if ((t & 7) == 0) s_inv[(t >> 3) + 48 * j] = 1.f / fmaxf(sqrtf(v), 1e-12f);
    }

    // ---- dump acc to smem C (aliases stages; all compute done) ----
    float* C = (float*)smem;
#pragma unroll
    for (int mt = 0; mt < 3; mt++)
#pragma unroll
        for (int nt = 0; nt < 8; nt++) {
            int rr = warpM * 48 + mt * 16 + (lane >> 2);
            int cc = warpN * 64 + nt * 8 + 2 * (lane & 3);
            *(float2*)&C[rr * CPAD + cc] = make_float2(acc[mt][nt][0], acc[mt][nt][1]);
            *(float2*)&C[(rr + 8) * CPAD + cc] = make_float2(acc[mt][nt][2], acc[mt][nt][3]);
        }
    __syncthreads();

    // ---- fused epilogue: per-thread batch column ----
    if (t < BATCH) {
        int n = t;
        int lab = g_labels[n];
        int cls0 = blockIdx.x * 48;
        float ssum = 0.f;
#pragma unroll 4
        for (int cl = 0; cl < 48; cl++) {
            int r = cl * 3;
            float c0 = C[r * CPAD + n] * s_inv[r];
            float c1 = C[(r + 1) * CPAD + n] * s_inv[r + 1];
            float c2 = C[(r + 2) * CPAD + n] * s_inv[r + 2];
            float cm = fmaxf(c0, fmaxf(c1, c2));
            int gc = cls0 + cl;
            if (gc < NCLS) {
                float x;
                if (gc == lab) {
                    float sine = sqrtf(fminf(fmaxf(1.f - cm * cm, 0.f), 1.f));
                    float phi = cm * COS_M - sine * SIN_M;
                    if (!(cm > TH_C)) phi = cm - MM_C;
                    x = 64.f * phi;
                    g_lab[n] = x;
                } else {
                    x = 64.f * cm;
                }
                ssum += __expf(x - 64.f);
            }
        }
        g_ps[(size_t)blockIdx.x * BATCH + n] = ssum;
    }
}

// ---------------- two-stage reduction ----------------
__global__ void k_part(void) {
    int t = threadIdx.x, b = blockIdx.x;   // FBLK blocks x 256 threads
    int k0 = b * 33, k1 = k0 + 33;
    if (k1 > NT) k1 = NT;
    float s = 0.f;
    for (int k = k0; k < k1; k++) s += g_ps[(size_t)k * BATCH + t];
    g_ps2[b * BATCH + t] = s;
}

__global__ void k_final(float* __restrict__ out) {
    int t = threadIdx.x;  // 256
    float s = 0.f;
#pragma unroll 8
    for (int k = 0; k < FBLK; k++) s += g_ps2[k * BATCH + t];
    float loss = 64.f + logf(s) - g_lab[t];
#pragma unroll
    for (int o = 16; o; o >>= 1) loss += __shfl_xor_sync(0xffffffffu, loss, o);
    __shared__ float sw[8];
    if ((t & 31) == 0) sw[t >> 5] = loss;
    __syncthreads();
    if (t == 0) {
        float tot = 0.f;
#pragma unroll
        for (int i = 0; i < 8; i++) tot += sw[i];
        out[0] = tot / (float)BATCH;
    }
}

// ---------------------------------------------------------------------------
extern "C" void kernel_launch(void* const* d_in, const int* in_sizes, int n_in,
                              void* d_out, int out_size) {
    const float* emb    = (const float*)d_in[0];
    const int*   labels = (const int*)d_in[1];
    const float* W      = (const float*)d_in[2];

    cudaFuncSetAttribute(k_gemm, cudaFuncAttributeMaxDynamicSharedMemorySize, SMEM_DYN);

    k_decode_labels<<<1, BATCH>>>(labels);
    k_prep<<<BATCH, 128>>>(emb);
    k_gemm<<<NT, 384, SMEM_DYN>>>(W);
    k_part<<<FBLK, BATCH>>>();
    k_final<<<1, BATCH>>>((float*)d_out);
}